// round 2
// baseline (speedup 1.0000x reference)
#include <cuda_runtime.h>
#include <math.h>

#define Bsz 16
#define Tn 16
#define FDIM 64
#define ODIM 8
#define NQ 10
#define NA 4
#define NROTS 80
#define QROTS 40
#define NS 1024
#define NANC 16
#define STATE_PER_B (NS*NANC)
#define TOTAL_AMPS (Bsz*STATE_PER_B)

__device__ float2 g_state[TOTAL_AMPS];   // [(b*16+a)<<10 | s]
__device__ float2 g_csn[Bsz*Tn*NROTS];
__device__ float2 g_qff[QROTS];
__device__ float2 g_M[3][256];
__device__ float2 g_v0[16];
__device__ float  g_ex[Bsz*30];

// ---------------------------------------------------------------- angles ----
__global__ void k_angles(const float* __restrict__ x,
                         const float* __restrict__ Wfp,
                         const float* __restrict__ bfp)
{
    int bt = blockIdx.x;
    int b = bt >> 4, t = bt & 15;
    __shared__ float h[64];
    int tid = threadIdx.x;
    if (tid < 64) {
        int f = tid;
        int k = f >> 1;
        float div = expf((float)(2*k) * (-logf(10000.0f) / 64.0f));
        float arg = (float)t * div;
        float pe = (f & 1) ? cosf(arg) : sinf(arg);
        h[f] = x[(b*64 + f)*16 + t] + pe;
    }
    __syncthreads();
    if (tid < NROTS) {
        float acc = bfp[tid];
        const float* w = Wfp + tid*64;
        #pragma unroll
        for (int f = 0; f < 64; ++f) acc += h[f]*w[f];
        float sg = 1.0f / (1.0f + expf(-acc));
        float sn, cs;
        sincosf(3.14159265358979323846f * sg, &sn, &cs);
        g_csn[bt*NROTS + tid] = make_float2(cs, sn);
    }
}

// -------------------------------------------------------------- setup -------
__global__ void k_setup(const float* __restrict__ prep_p,
                        const float* __restrict__ sig_ang,
                        const float* __restrict__ qff_p)
{
    __shared__ float2 sU[16][16];
    int t = threadIdx.x;
    if (t < 16) {
        float2 v[16];
        #pragma unroll
        for (int i = 0; i < 16; ++i) v[i] = make_float2(0.f, 0.f);
        v[t] = make_float2(1.f, 0.f);
        for (int ly = 0; ly < 4; ++ly) {
            for (int qi = 0; qi < 4; ++qi) {
                int p = 3 - qi;
                float thy = prep_p[(ly*4 + qi)*2 + 0];
                float thz = prep_p[(ly*4 + qi)*2 + 1];
                float c, s;
                sincosf(0.5f*thy, &s, &c);
                for (int m = 0; m < 8; ++m) {
                    int i0 = ((m >> p) << (p+1)) | (m & ((1 << p) - 1));
                    int i1 = i0 | (1 << p);
                    float2 a0 = v[i0], a1 = v[i1];
                    v[i0] = make_float2(c*a0.x - s*a1.x, c*a0.y - s*a1.y);
                    v[i1] = make_float2(s*a0.x + c*a1.x, s*a0.y + c*a1.y);
                }
                float cz, sz;
                sincosf(0.5f*thz, &sz, &cz);
                for (int i = 0; i < 16; ++i) {
                    float im = ((i >> p) & 1) ? sz : -sz;
                    float2 a = v[i];
                    v[i] = make_float2(cz*a.x - im*a.y, cz*a.y + im*a.x);
                }
            }
            for (int i = 0; i < 3; ++i) {
                int pc = 3 - i, pt = 2 - i;
                for (int idx = 0; idx < 16; ++idx) {
                    if (((idx >> pc) & 1) == 1 && ((idx >> pt) & 1) == 0) {
                        int j = idx | (1 << pt);
                        float2 tmp = v[idx]; v[idx] = v[j]; v[j] = tmp;
                    }
                }
            }
        }
        #pragma unroll
        for (int r = 0; r < 16; ++r) sU[r][t] = v[r];
    }
    __syncthreads();
    if (t < 16) {
        float c0, s0;
        sincosf(sig_ang[0], &s0, &c0);
        float2 u = sU[t][0];
        g_v0[t] = make_float2(c0*u.x - s0*u.y, c0*u.y + s0*u.x);
    }
    if (t >= 192 && t < 192 + QROTS) {
        float c, s;
        sincosf(0.5f * qff_p[t - 192], &s, &c);
        g_qff[t - 192] = make_float2(c, s);
    }
    // M build: 256 threads, one (j,k) entry each
    {
        int j = t >> 4, k = t & 15;
        for (int m = 0; m < 2; ++m) {
            float cp, sp;
            sincosf(sig_ang[m+1], &sp, &cp);
            float2 acc = make_float2(0.f, 0.f);
            #pragma unroll
            for (int a = 0; a < 16; ++a) {
                float2 uja = sU[j][a];
                float2 uka = sU[k][a];
                float dr = cp, di = (a == 0) ? sp : -sp;
                float2 dc = make_float2(dr*uka.x + di*uka.y, di*uka.x - dr*uka.y);
                acc.x += uja.x*dc.x - uja.y*dc.y;
                acc.y += uja.x*dc.y + uja.y*dc.x;
            }
            g_M[m][j*16 + k] = acc;
        }
        float cp, sp;
        sincosf(sig_ang[3], &sp, &cp);
        float dr = cp, di = (j == 0) ? sp : -sp;
        float2 u2 = sU[k][j];
        g_M[2][j*16 + k] = make_float2(dr*u2.x + di*u2.y, di*u2.x - dr*u2.y);
    }
}

// --------------------------------------------------------- gate tables ------
__host__ __device__ constexpr int g_kind_f(int r) { return (r/10) & 1; }
__host__ __device__ constexpr int g_pc_f(int r) {
    if (r < 10) return 9 - r;
    if (r < 20) return r - 10;
    if (r < 30) return 9 - (r - 20);
    int j = r - 30;
    return j == 0 ? 0 : (j == 1 ? 9 : 10 - j);
}
__host__ __device__ constexpr int g_pt_f(int r) {
    if (r < 10 || (r >= 20 && r < 30)) return 0;
    if (r < 20) { int j = r - 10; return j == 0 ? 9 : j - 1; }
    int j = r - 30;
    return j == 0 ? 1 : (j == 1 ? 0 : 11 - j);
}

// one gate, fully compile-time indices -> state stays in registers
template<bool ADJ, int R>
__device__ __forceinline__ void do_gate(float2* v, const float2* __restrict__ sang, int lane)
{
    constexpr int r    = ADJ ? (39 - R) : R;
    constexpr int kind = g_kind_f(r);
    constexpr int pc   = g_pc_f(r);
    constexpr int pt   = g_pt_f(r);
    float2 cs = sang[r];
    float cc = cs.x;
    float ss = ADJ ? -cs.y : cs.y;

    if constexpr (kind == 0) {
        if constexpr (pc >= 5) {                     // RY on register bit
            constexpr int pb = pc - 5;
            #pragma unroll
            for (int m = 0; m < 16; ++m) {
                int i0 = ((m >> pb) << (pb+1)) | (m & ((1 << pb) - 1));
                int i1 = i0 | (1 << pb);
                float2 a0 = v[i0], a1 = v[i1];
                v[i0] = make_float2(cc*a0.x - ss*a1.x, cc*a0.y - ss*a1.y);
                v[i1] = make_float2(ss*a0.x + cc*a1.x, ss*a0.y + cc*a1.y);
            }
        } else {                                     // RY on lane bit
            float sg = ((lane >> pc) & 1) ? ss : -ss;
            #pragma unroll
            for (int q = 0; q < 32; ++q) {
                float px = __shfl_xor_sync(0xffffffffu, v[q].x, 1 << pc);
                float py = __shfl_xor_sync(0xffffffffu, v[q].y, 1 << pc);
                v[q].x = cc*v[q].x + sg*px;
                v[q].y = cc*v[q].y + sg*py;
            }
        }
    } else {
        if constexpr (pc >= 5 && pt >= 5) {          // CRX: both reg bits
            constexpr int pcb = pc - 5, ptb = pt - 5;
            #pragma unroll
            for (int i = 0; i < 32; ++i) {
                if ((((i >> pcb) & 1) == 1) && (((i >> ptb) & 1) == 0)) {
                    int i1 = i | (1 << ptb);
                    float2 a0 = v[i], a1 = v[i1];
                    v[i]  = make_float2(cc*a0.x + ss*a1.y, cc*a0.y - ss*a1.x);
                    v[i1] = make_float2(cc*a1.x + ss*a0.y, cc*a1.y - ss*a0.x);
                }
            }
        } else if constexpr (pc >= 5) {              // control reg, target lane
            constexpr int pcb = pc - 5;
            #pragma unroll
            for (int q = 0; q < 32; ++q) {
                if ((q >> pcb) & 1) {
                    float px = __shfl_xor_sync(0xffffffffu, v[q].x, 1 << pt);
                    float py = __shfl_xor_sync(0xffffffffu, v[q].y, 1 << pt);
                    v[q] = make_float2(cc*v[q].x + ss*py, cc*v[q].y - ss*px);
                }
            }
        } else if constexpr (pt >= 5) {              // control lane, target reg
            constexpr int ptb = pt - 5;
            bool act = (lane >> pc) & 1;
            #pragma unroll
            for (int m = 0; m < 16; ++m) {
                int i0 = ((m >> ptb) << (ptb+1)) | (m & ((1 << ptb) - 1));
                int i1 = i0 | (1 << ptb);
                float2 a0 = v[i0], a1 = v[i1];
                float2 n0 = make_float2(cc*a0.x + ss*a1.y, cc*a0.y - ss*a1.x);
                float2 n1 = make_float2(cc*a1.x + ss*a0.y, cc*a1.y - ss*a0.x);
                if (act) { v[i0] = n0; v[i1] = n1; }
            }
        } else {                                     // both lane bits
            bool act = (lane >> pc) & 1;
            #pragma unroll
            for (int q = 0; q < 32; ++q) {
                float px = __shfl_xor_sync(0xffffffffu, v[q].x, 1 << pt);
                float py = __shfl_xor_sync(0xffffffffu, v[q].y, 1 << pt);
                if (act) v[q] = make_float2(cc*v[q].x + ss*py, cc*v[q].y - ss*px);
            }
        }
    }
}

template<bool ADJ, int R>
__device__ __forceinline__ void run_gates(float2* v, const float2* __restrict__ sang, int lane)
{
    do_gate<ADJ, R>(v, sang, lane);
    if constexpr (R + 1 < 40) run_gates<ADJ, R+1>(v, sang, lane);
}

// ------------------------------------------------------------- select -------
// MODE 0: forward 2 layers; MODE 1: adjoint 2 layers; MODE 2: qff 1 layer.
template<int MODE>
__global__ void __launch_bounds__(32) k_sel(int initFlag)
{
    int c = blockIdx.x;
    int lane = threadIdx.x;
    __shared__ float2 sang[80];
    if constexpr (MODE == 2) {
        if (lane < 8)
            #pragma unroll
            for (int q = 0; q < 5; ++q) sang[lane*5 + q] = g_qff[lane*5 + q];
    } else {
        const float2* ang = g_csn + c*NROTS;
        #pragma unroll
        for (int q = 0; q < 80; q += 32)
            if (q + lane < 80) sang[q + lane] = ang[q + lane];
    }
    __syncwarp();

    float2 v[32];
    float2* gb = g_state + ((size_t)c << 10);
    if (initFlag) {
        #pragma unroll
        for (int q = 0; q < 32; ++q) v[q] = make_float2(0.f, 0.f);
        if (lane == 0) v[0] = g_v0[c & 15];
    } else {
        #pragma unroll
        for (int q = 0; q < 32; ++q) v[q] = gb[q*32 + lane];
    }

    if constexpr (MODE == 0) {
        run_gates<false, 0>(v, sang, lane);
        run_gates<false, 0>(v, sang + 40, lane);
    } else if constexpr (MODE == 1) {
        run_gates<true, 0>(v, sang + 40, lane);
        run_gates<true, 0>(v, sang, lane);
    } else {
        run_gates<false, 0>(v, sang, lane);
    }

    #pragma unroll
    for (int q = 0; q < 32; ++q) gb[q*32 + lane] = v[q];
}

// ---------------------------------------------------------- ancilla mat -----
__global__ void __launch_bounds__(256) k_anc(int mi)
{
    int bk = blockIdx.x;
    int b = bk >> 6, s0 = (bk & 63) << 4;
    __shared__ float2 vin[16][17];
    __shared__ float2 sM[256];
    int tid = threadIdx.x;
    int a = tid >> 4, sl = tid & 15;
    sM[tid] = g_M[mi][tid];
    size_t idx = (((size_t)(b << 4) | a) << 10) + s0 + sl;
    vin[a][sl] = g_state[idx];
    __syncthreads();
    float2 acc = make_float2(0.f, 0.f);
    #pragma unroll
    for (int k2 = 0; k2 < 16; ++k2) {
        float2 m = sM[a*16 + k2];
        float2 vv = vin[k2][sl];
        acc.x += m.x*vv.x - m.y*vv.y;
        acc.y += m.x*vv.y + m.y*vv.x;
    }
    g_state[idx] = acc;
}

// ------------------------------------------------------------ expvals -------
__global__ void __launch_bounds__(256) k_exp()
{
    int blk = blockIdx.x;           // 16*10
    int b = blk / 10, i = blk % 10;
    int p = 9 - i;
    const float2* st = g_state + ((size_t)b << 14);
    __shared__ float red[8][3];
    int tid = threadIdx.x;

    float cr = 0.f, cim = 0.f, zz = 0.f;
    for (int pk = tid; pk < 8192; pk += 256) {
        int a = pk >> 9, m = pk & 511;
        int s0 = ((m >> p) << (p+1)) | (m & ((1 << p) - 1));
        int f0 = (a << 10) | s0;
        float2 a0 = st[f0];
        float2 a1 = st[f0 | (1 << p)];
        cr  += a0.x*a1.x + a0.y*a1.y;
        cim += a0.x*a1.y - a0.y*a1.x;
        zz  += (a0.x*a0.x + a0.y*a0.y) - (a1.x*a1.x + a1.y*a1.y);
    }
    #pragma unroll
    for (int off = 16; off; off >>= 1) {
        cr  += __shfl_down_sync(0xffffffffu, cr,  off);
        cim += __shfl_down_sync(0xffffffffu, cim, off);
        zz  += __shfl_down_sync(0xffffffffu, zz,  off);
    }
    if ((tid & 31) == 0) {
        int w = tid >> 5;
        red[w][0] = cr; red[w][1] = cim; red[w][2] = zz;
    }
    __syncthreads();
    if (tid == 0) {
        float A = 0.f, Bv = 0.f, C = 0.f;
        #pragma unroll
        for (int w = 0; w < 8; ++w) { A += red[w][0]; Bv += red[w][1]; C += red[w][2]; }
        g_ex[b*30 + i]      = 2.f * A;
        g_ex[b*30 + 10 + i] = 2.f * Bv;
        g_ex[b*30 + 20 + i] = C;
    }
}

__global__ void k_out(const float* __restrict__ W_out,
                      const float* __restrict__ b_out,
                      float* __restrict__ out)
{
    int t = threadIdx.x;            // 128 = 16 b * 8 o
    int b = t >> 3, o = t & 7;
    float acc = b_out[o];
    #pragma unroll
    for (int j = 0; j < 30; ++j) acc += W_out[o*30 + j] * g_ex[b*30 + j];
    out[b*ODIM + o] = acc;
}

// ------------------------------------------------------------ launch --------
extern "C" void kernel_launch(void* const* d_in, const int* in_sizes, int n_in,
                              void* d_out, int out_size)
{
    const float* x       = (const float*)d_in[0];
    const float* W_fp    = (const float*)d_in[1];
    const float* b_fp    = (const float*)d_in[2];
    const float* prep_p  = (const float*)d_in[3];
    const float* sig_ang = (const float*)d_in[4];
    const float* qff_p   = (const float*)d_in[5];
    const float* W_out   = (const float*)d_in[6];
    const float* b_out   = (const float*)d_in[7];
    float* out = (float*)d_out;

    k_angles<<<Bsz*Tn, 128>>>(x, W_fp, b_fp);
    k_setup<<<1, 256>>>(prep_p, sig_ang, qff_p);

    k_sel<0><<<256, 32>>>(1);     // k=0 forward (fused init)
    k_anc<<<1024, 256>>>(0);
    k_sel<1><<<256, 32>>>(0);     // k=1 adjoint
    k_anc<<<1024, 256>>>(1);
    k_sel<0><<<256, 32>>>(0);     // k=2 forward
    k_anc<<<1024, 256>>>(2);

    k_sel<2><<<256, 32>>>(0);     // qff layer

    k_exp<<<Bsz*10, 256>>>();
    k_out<<<1, 128>>>(W_out, b_out, out);
}

// round 3
// speedup vs baseline: 1.3497x; 1.3497x over previous
#include <cuda_runtime.h>
#include <math.h>

#define Bsz 16
#define Tn 16
#define FDIM 64
#define ODIM 8
#define NQ 10
#define NA 4
#define NROTS 80
#define QROTS 40
#define NS 1024
#define NANC 16
#define STATE_PER_B (NS*NANC)
#define TOTAL_AMPS (Bsz*STATE_PER_B)

__device__ float4 g_state4[TOTAL_AMPS/2];   // 16B-aligned; viewed as float2
#define G_STATE ((float2*)g_state4)
__device__ float2 g_csn[Bsz*Tn*NROTS];
__device__ float2 g_qff[QROTS];
__device__ float2 g_M[3][256];
__device__ float2 g_v0[16];
__device__ float  g_ex[Bsz*30];

// ---------------------------------------------------------------- angles ----
__global__ void k_angles(const float* __restrict__ x,
                         const float* __restrict__ Wfp,
                         const float* __restrict__ bfp)
{
    int bt = blockIdx.x;
    int b = bt >> 4, t = bt & 15;
    __shared__ float h[64];
    int tid = threadIdx.x;
    if (tid < 64) {
        int f = tid;
        int k = f >> 1;
        float div = expf((float)(2*k) * (-logf(10000.0f) / 64.0f));
        float arg = (float)t * div;
        float pe = (f & 1) ? cosf(arg) : sinf(arg);
        h[f] = x[(b*64 + f)*16 + t] + pe;
    }
    __syncthreads();
    if (tid < NROTS) {
        float acc = bfp[tid];
        const float* w = Wfp + tid*64;
        #pragma unroll
        for (int f = 0; f < 64; ++f) acc += h[f]*w[f];
        float sg = 1.0f / (1.0f + expf(-acc));
        float sn, cs;
        sincosf(3.14159265358979323846f * sg, &sn, &cs);
        g_csn[bt*NROTS + tid] = make_float2(cs, sn);
    }
}

// -------------------------------------------------------------- setup -------
__global__ void k_setup(const float* __restrict__ prep_p,
                        const float* __restrict__ sig_ang,
                        const float* __restrict__ qff_p)
{
    __shared__ float2 sU[16][16];
    int t = threadIdx.x;
    if (t < 16) {
        float2 v[16];
        #pragma unroll
        for (int i = 0; i < 16; ++i) v[i] = make_float2(0.f, 0.f);
        v[t] = make_float2(1.f, 0.f);
        for (int ly = 0; ly < 4; ++ly) {
            for (int qi = 0; qi < 4; ++qi) {
                int p = 3 - qi;
                float thy = prep_p[(ly*4 + qi)*2 + 0];
                float thz = prep_p[(ly*4 + qi)*2 + 1];
                float c, s;
                sincosf(0.5f*thy, &s, &c);
                for (int m = 0; m < 8; ++m) {
                    int i0 = ((m >> p) << (p+1)) | (m & ((1 << p) - 1));
                    int i1 = i0 | (1 << p);
                    float2 a0 = v[i0], a1 = v[i1];
                    v[i0] = make_float2(c*a0.x - s*a1.x, c*a0.y - s*a1.y);
                    v[i1] = make_float2(s*a0.x + c*a1.x, s*a0.y + c*a1.y);
                }
                float cz, sz;
                sincosf(0.5f*thz, &sz, &cz);
                for (int i = 0; i < 16; ++i) {
                    float im = ((i >> p) & 1) ? sz : -sz;
                    float2 a = v[i];
                    v[i] = make_float2(cz*a.x - im*a.y, cz*a.y + im*a.x);
                }
            }
            for (int i = 0; i < 3; ++i) {
                int pc = 3 - i, pt = 2 - i;
                for (int idx = 0; idx < 16; ++idx) {
                    if (((idx >> pc) & 1) == 1 && ((idx >> pt) & 1) == 0) {
                        int j = idx | (1 << pt);
                        float2 tmp = v[idx]; v[idx] = v[j]; v[j] = tmp;
                    }
                }
            }
        }
        #pragma unroll
        for (int r = 0; r < 16; ++r) sU[r][t] = v[r];
    }
    __syncthreads();
    if (t < 16) {
        float c0, s0;
        sincosf(sig_ang[0], &s0, &c0);
        float2 u = sU[t][0];
        g_v0[t] = make_float2(c0*u.x - s0*u.y, c0*u.y + s0*u.x);
    }
    if (t >= 192 && t < 192 + QROTS) {
        float c, s;
        sincosf(0.5f * qff_p[t - 192], &s, &c);
        g_qff[t - 192] = make_float2(c, s);
    }
    {
        int j = t >> 4, k = t & 15;
        for (int m = 0; m < 2; ++m) {
            float cp, sp;
            sincosf(sig_ang[m+1], &sp, &cp);
            float2 acc = make_float2(0.f, 0.f);
            #pragma unroll
            for (int a = 0; a < 16; ++a) {
                float2 uja = sU[j][a];
                float2 uka = sU[k][a];
                float dr = cp, di = (a == 0) ? sp : -sp;
                float2 dc = make_float2(dr*uka.x + di*uka.y, di*uka.x - dr*uka.y);
                acc.x += uja.x*dc.x - uja.y*dc.y;
                acc.y += uja.x*dc.y + uja.y*dc.x;
            }
            g_M[m][j*16 + k] = acc;
        }
        float cp, sp;
        sincosf(sig_ang[3], &sp, &cp);
        float dr = cp, di = (j == 0) ? sp : -sp;
        float2 u2 = sU[k][j];
        g_M[2][j*16 + k] = make_float2(dr*u2.x + di*u2.y, di*u2.x - dr*u2.y);
    }
}

// ------------------------------------------------------- gate primitives ----
// state: v[reg] at lane; amplitude s: lane = s[4:0], reg = s[9:5].

template<int PB>
__device__ __forceinline__ void ry_reg(float2* v, float cc, float ss)
{
    #pragma unroll
    for (int m = 0; m < 16; ++m) {
        int i0 = ((m >> PB) << (PB+1)) | (m & ((1 << PB) - 1));
        int i1 = i0 | (1 << PB);
        float2 a0 = v[i0], a1 = v[i1];
        v[i0] = make_float2(cc*a0.x - ss*a1.x, cc*a0.y - ss*a1.y);
        v[i1] = make_float2(ss*a0.x + cc*a1.x, ss*a0.y + cc*a1.y);
    }
}

__device__ __forceinline__ void ry_lane(float2* v, int pl, float cc, float ss, int lane)
{
    float sg = ((lane >> pl) & 1) ? ss : -ss;
    int mk = 1 << pl;
    #pragma unroll
    for (int q = 0; q < 32; ++q) {
        float px = __shfl_xor_sync(0xffffffffu, v[q].x, mk);
        float py = __shfl_xor_sync(0xffffffffu, v[q].y, mk);
        v[q].x = cc*v[q].x + sg*px;
        v[q].y = cc*v[q].y + sg*py;
    }
}

template<int PCB, int PTB>
__device__ __forceinline__ void crx_rr(float2* v, float cc, float ss)
{
    #pragma unroll
    for (int i = 0; i < 32; ++i) {
        if ((((i >> PCB) & 1) == 1) && (((i >> PTB) & 1) == 0)) {
            int i1 = i | (1 << PTB);
            float2 a0 = v[i], a1 = v[i1];
            v[i]  = make_float2(cc*a0.x + ss*a1.y, cc*a0.y - ss*a1.x);
            v[i1] = make_float2(cc*a1.x + ss*a0.y, cc*a1.y - ss*a0.x);
        }
    }
}

__device__ __forceinline__ void crx_ll(float2* v, int pc, int pt, float cc, float ss, int lane)
{
    int mk = 1 << pt;
    bool act = (lane >> pc) & 1;
    float ccl = act ? cc : 1.f;
    float ssl = act ? ss : 0.f;
    #pragma unroll
    for (int q = 0; q < 32; ++q) {
        float px = __shfl_xor_sync(0xffffffffu, v[q].x, mk);
        float py = __shfl_xor_sync(0xffffffffu, v[q].y, mk);
        float nx = ccl*v[q].x + ssl*py;
        float ny = ccl*v[q].y - ssl*px;
        v[q].x = nx; v[q].y = ny;
    }
}

// control on lane bit pc (runtime), target on reg bit PTB
template<int PTB>
__device__ __forceinline__ void crx_lr(float2* v, int pc, float cc, float ss, int lane)
{
    bool act = (lane >> pc) & 1;
    float ccl = act ? cc : 1.f;
    float ssl = act ? ss : 0.f;
    #pragma unroll
    for (int m = 0; m < 16; ++m) {
        int i0 = ((m >> PTB) << (PTB+1)) | (m & ((1 << PTB) - 1));
        int i1 = i0 | (1 << PTB);
        float2 a0 = v[i0], a1 = v[i1];
        v[i0] = make_float2(ccl*a0.x + ssl*a1.y, ccl*a0.y - ssl*a1.x);
        v[i1] = make_float2(ccl*a1.x + ssl*a0.y, ccl*a1.y - ssl*a0.x);
    }
}

// control on reg bit PCB, target on lane bit pt (runtime)
template<int PCB>
__device__ __forceinline__ void crx_rl(float2* v, int pt, float cc, float ss, int lane)
{
    int mk = 1 << pt;
    #pragma unroll
    for (int q = 0; q < 32; ++q) {
        if ((q >> PCB) & 1) {
            float px = __shfl_xor_sync(0xffffffffu, v[q].x, mk);
            float py = __shfl_xor_sync(0xffffffffu, v[q].y, mk);
            v[q] = make_float2(cc*v[q].x + ss*py, cc*v[q].y - ss*px);
        }
    }
}

// -------------------------------------------------------- layer pieces ------
// ang = 10 RY angles for this sub-layer (angle index = qubit q).
__device__ __forceinline__ void ry_all(float2* v, const float2* __restrict__ ang,
                                       float sgn, int lane)
{
    { float2 cs = ang[4]; ry_reg<0>(v, cs.x, sgn*cs.y); }
    { float2 cs = ang[3]; ry_reg<1>(v, cs.x, sgn*cs.y); }
    { float2 cs = ang[2]; ry_reg<2>(v, cs.x, sgn*cs.y); }
    { float2 cs = ang[1]; ry_reg<3>(v, cs.x, sgn*cs.y); }
    { float2 cs = ang[0]; ry_reg<4>(v, cs.x, sgn*cs.y); }
    #pragma unroll 1
    for (int pl = 0; pl < 5; ++pl) {
        float2 cs = ang[9 - pl];
        ry_lane(v, pl, cs.x, sgn*cs.y, lane);
    }
}

// ring down, forward order j = 0..9; ang = 10 CRX angles
__device__ __forceinline__ void ring_down(float2* v, const float2* __restrict__ ang,
                                          float sgn, int lane)
{
    { float2 cs = ang[0]; crx_lr<4>(v, 0, cs.x, sgn*cs.y, lane); }     // (0,9)
    #pragma unroll 1
    for (int j = 1; j <= 4; ++j) {                                     // (j, j-1)
        float2 cs = ang[j]; crx_ll(v, j, j-1, cs.x, sgn*cs.y, lane);
    }
    { float2 cs = ang[5]; crx_rl<0>(v, 4, cs.x, sgn*cs.y, lane); }     // (5,4)
    { float2 cs = ang[6]; crx_rr<1,0>(v, cs.x, sgn*cs.y); }            // (6,5)
    { float2 cs = ang[7]; crx_rr<2,1>(v, cs.x, sgn*cs.y); }            // (7,6)
    { float2 cs = ang[8]; crx_rr<3,2>(v, cs.x, sgn*cs.y); }            // (8,7)
    { float2 cs = ang[9]; crx_rr<4,3>(v, cs.x, sgn*cs.y); }            // (9,8)
}

__device__ __forceinline__ void ring_down_rev(float2* v, const float2* __restrict__ ang,
                                              float sgn, int lane)
{
    { float2 cs = ang[9]; crx_rr<4,3>(v, cs.x, sgn*cs.y); }
    { float2 cs = ang[8]; crx_rr<3,2>(v, cs.x, sgn*cs.y); }
    { float2 cs = ang[7]; crx_rr<2,1>(v, cs.x, sgn*cs.y); }
    { float2 cs = ang[6]; crx_rr<1,0>(v, cs.x, sgn*cs.y); }
    { float2 cs = ang[5]; crx_rl<0>(v, 4, cs.x, sgn*cs.y, lane); }
    #pragma unroll 1
    for (int j = 4; j >= 1; --j) {
        float2 cs = ang[j]; crx_ll(v, j, j-1, cs.x, sgn*cs.y, lane);
    }
    { float2 cs = ang[0]; crx_lr<4>(v, 0, cs.x, sgn*cs.y, lane); }
}

// ring up, forward order j = 0..9
__device__ __forceinline__ void ring_up(float2* v, const float2* __restrict__ ang,
                                        float sgn, int lane)
{
    { float2 cs = ang[0]; crx_ll(v, 0, 1, cs.x, sgn*cs.y, lane); }     // (0,1)
    { float2 cs = ang[1]; crx_rl<4>(v, 0, cs.x, sgn*cs.y, lane); }     // (9,0)
    { float2 cs = ang[2]; crx_rr<3,4>(v, cs.x, sgn*cs.y); }            // (8,9)
    { float2 cs = ang[3]; crx_rr<2,3>(v, cs.x, sgn*cs.y); }            // (7,8)
    { float2 cs = ang[4]; crx_rr<1,2>(v, cs.x, sgn*cs.y); }            // (6,7)
    { float2 cs = ang[5]; crx_rr<0,1>(v, cs.x, sgn*cs.y); }            // (5,6)
    { float2 cs = ang[6]; crx_lr<0>(v, 4, cs.x, sgn*cs.y, lane); }     // (4,5)
    #pragma unroll 1
    for (int j = 7; j <= 9; ++j) {                                     // (10-j, 11-j)
        float2 cs = ang[j]; crx_ll(v, 10-j, 11-j, cs.x, sgn*cs.y, lane);
    }
}

__device__ __forceinline__ void ring_up_rev(float2* v, const float2* __restrict__ ang,
                                            float sgn, int lane)
{
    #pragma unroll 1
    for (int j = 9; j >= 7; --j) {
        float2 cs = ang[j]; crx_ll(v, 10-j, 11-j, cs.x, sgn*cs.y, lane);
    }
    { float2 cs = ang[6]; crx_lr<0>(v, 4, cs.x, sgn*cs.y, lane); }
    { float2 cs = ang[5]; crx_rr<0,1>(v, cs.x, sgn*cs.y); }
    { float2 cs = ang[4]; crx_rr<1,2>(v, cs.x, sgn*cs.y); }
    { float2 cs = ang[3]; crx_rr<2,3>(v, cs.x, sgn*cs.y); }
    { float2 cs = ang[2]; crx_rr<3,4>(v, cs.x, sgn*cs.y); }
    { float2 cs = ang[1]; crx_rl<4>(v, 0, cs.x, sgn*cs.y, lane); }
    { float2 cs = ang[0]; crx_ll(v, 0, 1, cs.x, sgn*cs.y, lane); }
}

// ------------------------------------------------------------- select -------
__global__ void __launch_bounds__(32) k_sel_f(int nlayers, int useQff, int initFlag)
{
    int c = blockIdx.x;
    int lane = threadIdx.x;
    __shared__ float2 sang[80];
    {
        const float2* src = useQff ? g_qff : (g_csn + c*NROTS);
        int ntot = nlayers * 40;
        for (int i = lane; i < ntot; i += 32) sang[i] = src[i];
    }
    __syncwarp();

    float2 v[32];
    float2* gb = G_STATE + ((size_t)c << 10);
    if (initFlag) {
        #pragma unroll
        for (int q = 0; q < 32; ++q) v[q] = make_float2(0.f, 0.f);
        if (lane == 0) v[0] = g_v0[c & 15];
    } else {
        #pragma unroll
        for (int q = 0; q < 32; ++q) v[q] = gb[q*32 + lane];
    }

    #pragma unroll 1
    for (int l = 0; l < nlayers; ++l) {
        const float2* a = sang + 40*l;
        ry_all(v, a, 1.f, lane);
        ring_down(v, a + 10, 1.f, lane);
        ry_all(v, a + 20, 1.f, lane);
        ring_up(v, a + 30, 1.f, lane);
    }

    #pragma unroll
    for (int q = 0; q < 32; ++q) gb[q*32 + lane] = v[q];
}

__global__ void __launch_bounds__(32) k_sel_a(int nlayers)
{
    int c = blockIdx.x;
    int lane = threadIdx.x;
    __shared__ float2 sang[80];
    {
        const float2* src = g_csn + c*NROTS;
        int ntot = nlayers * 40;
        for (int i = lane; i < ntot; i += 32) sang[i] = src[i];
    }
    __syncwarp();

    float2 v[32];
    float2* gb = G_STATE + ((size_t)c << 10);
    #pragma unroll
    for (int q = 0; q < 32; ++q) v[q] = gb[q*32 + lane];

    #pragma unroll 1
    for (int l = nlayers - 1; l >= 0; --l) {
        const float2* a = sang + 40*l;
        ring_up_rev(v, a + 30, -1.f, lane);
        ry_all(v, a + 20, -1.f, lane);
        ring_down_rev(v, a + 10, -1.f, lane);
        ry_all(v, a, -1.f, lane);
    }

    #pragma unroll
    for (int q = 0; q < 32; ++q) gb[q*32 + lane] = v[q];
}

// ---------------------------------------------------------- ancilla mat -----
__global__ void __launch_bounds__(256) k_anc(int mi)
{
    int bk = blockIdx.x;               // 16 b * 32 s-groups of 32
    int b = bk >> 5, s0 = (bk & 31) << 5;
    __shared__ float2 vin[16][33];
    __shared__ float2 sM[256];
    int tid = threadIdx.x;
    int a = tid >> 4, sl = (tid & 15) * 2;
    sM[tid] = g_M[mi][tid];
    size_t idx = (((size_t)(b*16 + a)) << 10) + s0 + sl;
    float4 t = *(const float4*)(G_STATE + idx);
    vin[a][sl]   = make_float2(t.x, t.y);
    vin[a][sl+1] = make_float2(t.z, t.w);
    __syncthreads();
    float2 acc0 = make_float2(0.f, 0.f), acc1 = make_float2(0.f, 0.f);
    #pragma unroll
    for (int k2 = 0; k2 < 16; ++k2) {
        float2 m = sM[a*16 + k2];
        float2 v0 = vin[k2][sl], v1 = vin[k2][sl+1];
        acc0.x += m.x*v0.x - m.y*v0.y; acc0.y += m.x*v0.y + m.y*v0.x;
        acc1.x += m.x*v1.x - m.y*v1.y; acc1.y += m.x*v1.y + m.y*v1.x;
    }
    *(float4*)(G_STATE + idx) = make_float4(acc0.x, acc0.y, acc1.x, acc1.y);
}

// ------------------------------------------------------------ expvals -------
__global__ void __launch_bounds__(256) k_exp()
{
    int blk = blockIdx.x;           // 16*10
    int b = blk / 10, i = blk % 10;
    int p = 9 - i;
    const float2* st = G_STATE + ((size_t)b << 14);
    __shared__ float red[8][3];
    int tid = threadIdx.x;

    float cr = 0.f, cim = 0.f, zz = 0.f;
    for (int pk = tid; pk < 8192; pk += 256) {
        int a = pk >> 9, m = pk & 511;
        int s0 = ((m >> p) << (p+1)) | (m & ((1 << p) - 1));
        int f0 = (a << 10) | s0;
        float2 a0 = st[f0];
        float2 a1 = st[f0 | (1 << p)];
        cr  += a0.x*a1.x + a0.y*a1.y;
        cim += a0.x*a1.y - a0.y*a1.x;
        zz  += (a0.x*a0.x + a0.y*a0.y) - (a1.x*a1.x + a1.y*a1.y);
    }
    #pragma unroll
    for (int off = 16; off; off >>= 1) {
        cr  += __shfl_down_sync(0xffffffffu, cr,  off);
        cim += __shfl_down_sync(0xffffffffu, cim, off);
        zz  += __shfl_down_sync(0xffffffffu, zz,  off);
    }
    if ((tid & 31) == 0) {
        int w = tid >> 5;
        red[w][0] = cr; red[w][1] = cim; red[w][2] = zz;
    }
    __syncthreads();
    if (tid == 0) {
        float A = 0.f, Bv = 0.f, C = 0.f;
        #pragma unroll
        for (int w = 0; w < 8; ++w) { A += red[w][0]; Bv += red[w][1]; C += red[w][2]; }
        g_ex[b*30 + i]      = 2.f * A;
        g_ex[b*30 + 10 + i] = 2.f * Bv;
        g_ex[b*30 + 20 + i] = C;
    }
}

__global__ void k_out(const float* __restrict__ W_out,
                      const float* __restrict__ b_out,
                      float* __restrict__ out)
{
    int t = threadIdx.x;            // 128 = 16 b * 8 o
    int b = t >> 3, o = t & 7;
    float acc = b_out[o];
    #pragma unroll
    for (int j = 0; j < 30; ++j) acc += W_out[o*30 + j] * g_ex[b*30 + j];
    out[b*ODIM + o] = acc;
}

// ------------------------------------------------------------ launch --------
extern "C" void kernel_launch(void* const* d_in, const int* in_sizes, int n_in,
                              void* d_out, int out_size)
{
    const float* x       = (const float*)d_in[0];
    const float* W_fp    = (const float*)d_in[1];
    const float* b_fp    = (const float*)d_in[2];
    const float* prep_p  = (const float*)d_in[3];
    const float* sig_ang = (const float*)d_in[4];
    const float* qff_p   = (const float*)d_in[5];
    const float* W_out   = (const float*)d_in[6];
    const float* b_out   = (const float*)d_in[7];
    float* out = (float*)d_out;

    k_angles<<<Bsz*Tn, 128>>>(x, W_fp, b_fp);
    k_setup<<<1, 256>>>(prep_p, sig_ang, qff_p);

    k_sel_f<<<256, 32>>>(2, 0, 1);   // k=0 forward (fused init)
    k_anc<<<512, 256>>>(0);
    k_sel_a<<<256, 32>>>(2);         // k=1 adjoint
    k_anc<<<512, 256>>>(1);
    k_sel_f<<<256, 32>>>(2, 0, 0);   // k=2 forward
    k_anc<<<512, 256>>>(2);

    k_sel_f<<<256, 32>>>(1, 1, 0);   // qff layer

    k_exp<<<Bsz*10, 256>>>();
    k_out<<<1, 128>>>(W_out, b_out, out);
}

// round 4
// speedup vs baseline: 1.5262x; 1.1307x over previous
#include <cuda_runtime.h>
#include <math.h>

#define Bsz 16
#define Tn 16
#define FDIM 64
#define ODIM 8
#define NQ 10
#define NA 4
#define NROTS 80
#define QROTS 40
#define NS 1024
#define NANC 16
#define STATE_PER_B (NS*NANC)
#define TOTAL_AMPS (Bsz*STATE_PER_B)

typedef unsigned long long u64;

__device__ float4 g_state4[TOTAL_AMPS/2];   // 16B-aligned; float2 / u64 views
#define G_STATE  ((float2*)g_state4)
#define G_STATEU ((u64*)g_state4)
__device__ float2 g_csn[Bsz*Tn*NROTS];
__device__ float2 g_qff[QROTS];
__device__ float2 g_M[3][256];
__device__ float2 g_v0[16];

// ------------------------------------------------------- packed f32x2 ops ---
__device__ __forceinline__ u64 pk2(float x, float y) {
    u64 r; asm("mov.b64 %0, {%1, %2};" : "=l"(r) : "f"(x), "f"(y)); return r;
}
__device__ __forceinline__ float2 upk(u64 a) {
    float2 f; asm("mov.b64 {%0, %1}, %2;" : "=f"(f.x), "=f"(f.y) : "l"(a)); return f;
}
__device__ __forceinline__ u64 mul2(u64 a, u64 b) {
    u64 d; asm("mul.rn.f32x2 %0, %1, %2;" : "=l"(d) : "l"(a), "l"(b)); return d;
}
__device__ __forceinline__ u64 fma2(u64 a, u64 b, u64 c) {
    u64 d; asm("fma.rn.f32x2 %0, %1, %2, %3;" : "=l"(d) : "l"(a), "l"(b), "l"(c)); return d;
}
__device__ __forceinline__ u64 swap2(u64 a) {
    float2 f = upk(a); return pk2(f.y, f.x);
}

// -------------------------------------------------- pre (angles + setup) ----
__global__ void __launch_bounds__(256) k_pre(const float* __restrict__ x,
                                             const float* __restrict__ Wfp,
                                             const float* __restrict__ bfp,
                                             const float* __restrict__ prep_p,
                                             const float* __restrict__ sig_ang,
                                             const float* __restrict__ qff_p)
{
    int tid = threadIdx.x;
    if (blockIdx.x < 256) {
        // ---- angles for (b,t) = blockIdx ----
        int bt = blockIdx.x;
        int b = bt >> 4, t = bt & 15;
        __shared__ float h[64];
        if (tid < 64) {
            int f = tid;
            int k = f >> 1;
            float div = expf((float)(2*k) * (-logf(10000.0f) / 64.0f));
            float arg = (float)t * div;
            float pe = (f & 1) ? cosf(arg) : sinf(arg);
            h[f] = x[(b*64 + f)*16 + t] + pe;
        }
        __syncthreads();
        if (tid < NROTS) {
            float acc = bfp[tid];
            const float* w = Wfp + tid*64;
            #pragma unroll
            for (int f = 0; f < 64; ++f) acc += h[f]*w[f];
            float sg = 1.0f / (1.0f + expf(-acc));
            float sn, cs;
            sincosf(3.14159265358979323846f * sg, &sn, &cs);
            g_csn[bt*NROTS + tid] = make_float2(cs, sn);
        }
        return;
    }
    // ---- setup block ----
    __shared__ float2 sU[16][16];
    int t = tid;
    if (t < 16) {
        float2 v[16];
        #pragma unroll
        for (int i = 0; i < 16; ++i) v[i] = make_float2(0.f, 0.f);
        v[t] = make_float2(1.f, 0.f);
        for (int ly = 0; ly < 4; ++ly) {
            for (int qi = 0; qi < 4; ++qi) {
                int p = 3 - qi;
                float thy = prep_p[(ly*4 + qi)*2 + 0];
                float thz = prep_p[(ly*4 + qi)*2 + 1];
                float c, s;
                sincosf(0.5f*thy, &s, &c);
                for (int m = 0; m < 8; ++m) {
                    int i0 = ((m >> p) << (p+1)) | (m & ((1 << p) - 1));
                    int i1 = i0 | (1 << p);
                    float2 a0 = v[i0], a1 = v[i1];
                    v[i0] = make_float2(c*a0.x - s*a1.x, c*a0.y - s*a1.y);
                    v[i1] = make_float2(s*a0.x + c*a1.x, s*a0.y + c*a1.y);
                }
                float cz, sz;
                sincosf(0.5f*thz, &sz, &cz);
                for (int i = 0; i < 16; ++i) {
                    float im = ((i >> p) & 1) ? sz : -sz;
                    float2 a = v[i];
                    v[i] = make_float2(cz*a.x - im*a.y, cz*a.y + im*a.x);
                }
            }
            for (int i = 0; i < 3; ++i) {
                int pc = 3 - i, pt = 2 - i;
                for (int idx = 0; idx < 16; ++idx) {
                    if (((idx >> pc) & 1) == 1 && ((idx >> pt) & 1) == 0) {
                        int j = idx | (1 << pt);
                        float2 tmp = v[idx]; v[idx] = v[j]; v[j] = tmp;
                    }
                }
            }
        }
        #pragma unroll
        for (int r = 0; r < 16; ++r) sU[r][t] = v[r];
    }
    __syncthreads();
    if (t < 16) {
        float c0, s0;
        sincosf(sig_ang[0], &s0, &c0);
        float2 u = sU[t][0];
        g_v0[t] = make_float2(c0*u.x - s0*u.y, c0*u.y + s0*u.x);
    }
    if (t >= 192 && t < 192 + QROTS) {
        float c, s;
        sincosf(0.5f * qff_p[t - 192], &s, &c);
        g_qff[t - 192] = make_float2(c, s);
    }
    {
        int j = t >> 4, k = t & 15;
        for (int m = 0; m < 2; ++m) {
            float cp, sp;
            sincosf(sig_ang[m+1], &sp, &cp);
            float2 acc = make_float2(0.f, 0.f);
            #pragma unroll
            for (int a = 0; a < 16; ++a) {
                float2 uja = sU[j][a];
                float2 uka = sU[k][a];
                float dr = cp, di = (a == 0) ? sp : -sp;
                float2 dc = make_float2(dr*uka.x + di*uka.y, di*uka.x - dr*uka.y);
                acc.x += uja.x*dc.x - uja.y*dc.y;
                acc.y += uja.x*dc.y + uja.y*dc.x;
            }
            g_M[m][j*16 + k] = acc;
        }
        float cp, sp;
        sincosf(sig_ang[3], &sp, &cp);
        float dr = cp, di = (j == 0) ? sp : -sp;
        float2 u2 = sU[k][j];
        g_M[2][j*16 + k] = make_float2(dr*u2.x + di*u2.y, di*u2.x - dr*u2.y);
    }
}

// ------------------------------------------------------- gate primitives ----
// state u64 v[32] packed (x,y); amplitude s: lane = s[4:0], reg = s[9:5].

template<int PB>
__device__ __forceinline__ void ry_reg(u64* v, u64 cc2, u64 ss2, u64 nss2)
{
    #pragma unroll
    for (int m = 0; m < 16; ++m) {
        int i0 = ((m >> PB) << (PB+1)) | (m & ((1 << PB) - 1));
        int i1 = i0 | (1 << PB);
        u64 a0 = v[i0], a1 = v[i1];
        v[i0] = fma2(cc2, a0, mul2(nss2, a1));
        v[i1] = fma2(cc2, a1, mul2(ss2, a0));
    }
}

__device__ __forceinline__ void ry_lane(u64* v, int pl, float cc, float ss, int lane)
{
    float sg = ((lane >> pl) & 1) ? ss : -ss;
    u64 cc2 = pk2(cc, cc), sg2 = pk2(sg, sg);
    int mk = 1 << pl;
    #pragma unroll
    for (int q = 0; q < 32; ++q) {
        float2 f = upk(v[q]);
        float px = __shfl_xor_sync(0xffffffffu, f.x, mk);
        float py = __shfl_xor_sync(0xffffffffu, f.y, mk);
        v[q] = fma2(cc2, v[q], mul2(sg2, pk2(px, py)));
    }
}

template<int PCB, int PTB>
__device__ __forceinline__ void crx_rr(u64* v, u64 cc2, u64 ssv2)   // ssv2=(ss,-ss)
{
    #pragma unroll
    for (int i = 0; i < 32; ++i) {
        if ((((i >> PCB) & 1) == 1) && (((i >> PTB) & 1) == 0)) {
            int i1 = i | (1 << PTB);
            u64 a0 = v[i], a1 = v[i1];
            v[i]  = fma2(cc2, a0, mul2(ssv2, swap2(a1)));
            v[i1] = fma2(cc2, a1, mul2(ssv2, swap2(a0)));
        }
    }
}

__device__ __forceinline__ void crx_ll(u64* v, int pc, int pt, float cc, float ss, int lane)
{
    bool act = (lane >> pc) & 1;
    float ccl = act ? cc : 1.f, ssl = act ? ss : 0.f;
    u64 cc2 = pk2(ccl, ccl), ssv2 = pk2(ssl, -ssl);
    int mk = 1 << pt;
    #pragma unroll
    for (int q = 0; q < 32; ++q) {
        float2 f = upk(v[q]);
        float px = __shfl_xor_sync(0xffffffffu, f.x, mk);
        float py = __shfl_xor_sync(0xffffffffu, f.y, mk);
        v[q] = fma2(cc2, v[q], mul2(ssv2, pk2(py, px)));
    }
}

template<int PTB>
__device__ __forceinline__ void crx_lr(u64* v, int pc, float cc, float ss, int lane)
{
    bool act = (lane >> pc) & 1;
    float ccl = act ? cc : 1.f, ssl = act ? ss : 0.f;
    u64 cc2 = pk2(ccl, ccl), ssv2 = pk2(ssl, -ssl);
    #pragma unroll
    for (int m = 0; m < 16; ++m) {
        int i0 = ((m >> PTB) << (PTB+1)) | (m & ((1 << PTB) - 1));
        int i1 = i0 | (1 << PTB);
        u64 a0 = v[i0], a1 = v[i1];
        v[i0] = fma2(cc2, a0, mul2(ssv2, swap2(a1)));
        v[i1] = fma2(cc2, a1, mul2(ssv2, swap2(a0)));
    }
}

template<int PCB>
__device__ __forceinline__ void crx_rl(u64* v, int pt, float cc, float ss, int lane)
{
    u64 cc2 = pk2(cc, cc), ssv2 = pk2(ss, -ss);
    int mk = 1 << pt;
    #pragma unroll
    for (int q = 0; q < 32; ++q) {
        if ((q >> PCB) & 1) {
            float2 f = upk(v[q]);
            float px = __shfl_xor_sync(0xffffffffu, f.x, mk);
            float py = __shfl_xor_sync(0xffffffffu, f.y, mk);
            v[q] = fma2(cc2, v[q], mul2(ssv2, pk2(py, px)));
        }
    }
}

// -------------------------------------------------------- layer pieces ------
__device__ __forceinline__ void mkry(float2 cs, float sgn, u64& cc2, u64& ss2, u64& nss2)
{
    float ss = sgn*cs.y;
    cc2 = pk2(cs.x, cs.x); ss2 = pk2(ss, ss); nss2 = pk2(-ss, -ss);
}

__device__ __forceinline__ void ry_all(u64* v, const float2* __restrict__ ang,
                                       float sgn, int lane)
{
    { u64 a,b,c; mkry(ang[4], sgn, a,b,c); ry_reg<0>(v,a,b,c); }
    { u64 a,b,c; mkry(ang[3], sgn, a,b,c); ry_reg<1>(v,a,b,c); }
    { u64 a,b,c; mkry(ang[2], sgn, a,b,c); ry_reg<2>(v,a,b,c); }
    { u64 a,b,c; mkry(ang[1], sgn, a,b,c); ry_reg<3>(v,a,b,c); }
    { u64 a,b,c; mkry(ang[0], sgn, a,b,c); ry_reg<4>(v,a,b,c); }
    #pragma unroll 1
    for (int pl = 0; pl < 5; ++pl) {
        float2 cs = ang[9 - pl];
        ry_lane(v, pl, cs.x, sgn*cs.y, lane);
    }
}

#define RRGATE(PCB,PTB,CS) { float2 cs_ = (CS); float ss_ = sgn*cs_.y; \
    crx_rr<PCB,PTB>(v, pk2(cs_.x,cs_.x), pk2(ss_,-ss_)); }

__device__ __forceinline__ void ring_down(u64* v, const float2* __restrict__ ang,
                                          float sgn, int lane)
{
    { float2 cs = ang[0]; crx_lr<4>(v, 0, cs.x, sgn*cs.y, lane); }     // (0,9)
    #pragma unroll 1
    for (int j = 1; j <= 4; ++j) {                                     // (j, j-1)
        float2 cs = ang[j]; crx_ll(v, j, j-1, cs.x, sgn*cs.y, lane);
    }
    { float2 cs = ang[5]; crx_rl<0>(v, 4, cs.x, sgn*cs.y, lane); }     // (5,4)
    RRGATE(1,0, ang[6])                                                // (6,5)
    RRGATE(2,1, ang[7])                                                // (7,6)
    RRGATE(3,2, ang[8])                                                // (8,7)
    RRGATE(4,3, ang[9])                                                // (9,8)
}

__device__ __forceinline__ void ring_down_rev(u64* v, const float2* __restrict__ ang,
                                              float sgn, int lane)
{
    RRGATE(4,3, ang[9])
    RRGATE(3,2, ang[8])
    RRGATE(2,1, ang[7])
    RRGATE(1,0, ang[6])
    { float2 cs = ang[5]; crx_rl<0>(v, 4, cs.x, sgn*cs.y, lane); }
    #pragma unroll 1
    for (int j = 4; j >= 1; --j) {
        float2 cs = ang[j]; crx_ll(v, j, j-1, cs.x, sgn*cs.y, lane);
    }
    { float2 cs = ang[0]; crx_lr<4>(v, 0, cs.x, sgn*cs.y, lane); }
}

__device__ __forceinline__ void ring_up(u64* v, const float2* __restrict__ ang,
                                        float sgn, int lane)
{
    { float2 cs = ang[0]; crx_ll(v, 0, 1, cs.x, sgn*cs.y, lane); }     // (0,1)
    { float2 cs = ang[1]; crx_rl<4>(v, 0, cs.x, sgn*cs.y, lane); }     // (9,0)
    RRGATE(3,4, ang[2])                                                // (8,9)
    RRGATE(2,3, ang[3])                                                // (7,8)
    RRGATE(1,2, ang[4])                                                // (6,7)
    RRGATE(0,1, ang[5])                                                // (5,6)
    { float2 cs = ang[6]; crx_lr<0>(v, 4, cs.x, sgn*cs.y, lane); }     // (4,5)
    #pragma unroll 1
    for (int j = 7; j <= 9; ++j) {                                     // (10-j, 11-j)
        float2 cs = ang[j]; crx_ll(v, 10-j, 11-j, cs.x, sgn*cs.y, lane);
    }
}

__device__ __forceinline__ void ring_up_rev(u64* v, const float2* __restrict__ ang,
                                            float sgn, int lane)
{
    #pragma unroll 1
    for (int j = 9; j >= 7; --j) {
        float2 cs = ang[j]; crx_ll(v, 10-j, 11-j, cs.x, sgn*cs.y, lane);
    }
    { float2 cs = ang[6]; crx_lr<0>(v, 4, cs.x, sgn*cs.y, lane); }
    RRGATE(0,1, ang[5])
    RRGATE(1,2, ang[4])
    RRGATE(2,3, ang[3])
    RRGATE(3,4, ang[2])
    { float2 cs = ang[1]; crx_rl<4>(v, 0, cs.x, sgn*cs.y, lane); }
    { float2 cs = ang[0]; crx_ll(v, 0, 1, cs.x, sgn*cs.y, lane); }
}

// ------------------------------------------------------------- select -------
__global__ void __launch_bounds__(32) k_sel_f(int nlayers, int useQff, int initFlag)
{
    int c = blockIdx.x;
    int lane = threadIdx.x;
    const float sgn = 1.f;
    __shared__ float2 sang[80];
    {
        const float2* src = useQff ? g_qff : (g_csn + c*NROTS);
        int ntot = nlayers * 40;
        for (int i = lane; i < ntot; i += 32) sang[i] = src[i];
    }
    __syncwarp();

    u64 v[32];
    u64* gb = G_STATEU + ((size_t)c << 10);
    if (initFlag) {
        #pragma unroll
        for (int q = 0; q < 32; ++q) v[q] = 0ull;
        if (lane == 0) { float2 f = g_v0[c & 15]; v[0] = pk2(f.x, f.y); }
    } else {
        #pragma unroll
        for (int q = 0; q < 32; ++q) v[q] = gb[q*32 + lane];
    }

    #pragma unroll 1
    for (int l = 0; l < nlayers; ++l) {
        const float2* a = sang + 40*l;
        ry_all(v, a, sgn, lane);
        ring_down(v, a + 10, sgn, lane);
        ry_all(v, a + 20, sgn, lane);
        ring_up(v, a + 30, sgn, lane);
    }

    #pragma unroll
    for (int q = 0; q < 32; ++q) gb[q*32 + lane] = v[q];
}

__global__ void __launch_bounds__(32) k_sel_a(int nlayers)
{
    int c = blockIdx.x;
    int lane = threadIdx.x;
    const float sgn = -1.f;
    __shared__ float2 sang[80];
    {
        const float2* src = g_csn + c*NROTS;
        int ntot = nlayers * 40;
        for (int i = lane; i < ntot; i += 32) sang[i] = src[i];
    }
    __syncwarp();

    u64 v[32];
    u64* gb = G_STATEU + ((size_t)c << 10);
    #pragma unroll
    for (int q = 0; q < 32; ++q) v[q] = gb[q*32 + lane];

    #pragma unroll 1
    for (int l = nlayers - 1; l >= 0; --l) {
        const float2* a = sang + 40*l;
        ring_up_rev(v, a + 30, sgn, lane);
        ry_all(v, a + 20, sgn, lane);
        ring_down_rev(v, a + 10, sgn, lane);
        ry_all(v, a, sgn, lane);
    }

    #pragma unroll
    for (int q = 0; q < 32; ++q) gb[q*32 + lane] = v[q];
}

// ---------------------------------------------------------- ancilla mat -----
__global__ void __launch_bounds__(256) k_anc(int mi)
{
    int bk = blockIdx.x;               // 16 b * 16 s-groups of 64
    int b = bk >> 4, s0 = (bk & 15) << 6;
    __shared__ float2 vin[16][64];
    __shared__ float2 sM[256];
    int tid = threadIdx.x;
    int a = tid >> 4, sj = tid & 15;
    sM[tid] = g_M[mi][tid];
    size_t base = (((size_t)(b*16 + a)) << 10) + s0 + sj;
    float2 in0 = G_STATE[base];
    float2 in1 = G_STATE[base + 16];
    float2 in2 = G_STATE[base + 32];
    float2 in3 = G_STATE[base + 48];
    vin[a][sj]      = in0;
    vin[a][sj + 16] = in1;
    vin[a][sj + 32] = in2;
    vin[a][sj + 48] = in3;
    __syncthreads();
    float2 acc0 = make_float2(0.f,0.f), acc1 = make_float2(0.f,0.f);
    float2 acc2 = make_float2(0.f,0.f), acc3 = make_float2(0.f,0.f);
    #pragma unroll
    for (int k2 = 0; k2 < 16; ++k2) {
        float2 m = sM[a*16 + k2];
        float2 w0 = vin[k2][sj],      w1 = vin[k2][sj + 16];
        float2 w2 = vin[k2][sj + 32], w3 = vin[k2][sj + 48];
        acc0.x += m.x*w0.x - m.y*w0.y; acc0.y += m.x*w0.y + m.y*w0.x;
        acc1.x += m.x*w1.x - m.y*w1.y; acc1.y += m.x*w1.y + m.y*w1.x;
        acc2.x += m.x*w2.x - m.y*w2.y; acc2.y += m.x*w2.y + m.y*w2.x;
        acc3.x += m.x*w3.x - m.y*w3.y; acc3.y += m.x*w3.y + m.y*w3.x;
    }
    G_STATE[base]      = acc0;
    G_STATE[base + 16] = acc1;
    G_STATE[base + 32] = acc2;
    G_STATE[base + 48] = acc3;
}

// ------------------------------------------------- expvals + output GEMM ----
__global__ void __launch_bounds__(640) k_exp_out(const float* __restrict__ W_out,
                                                 const float* __restrict__ b_out,
                                                 float* __restrict__ out)
{
    int b = blockIdx.x;
    int tid = threadIdx.x, w = tid >> 5, lane = tid & 31;
    const float2* st = G_STATE + ((size_t)b << 14);
    __shared__ float red[20][3];
    __shared__ float ex[30];

    {
        int qi = w % 10, half = w / 10;     // warp: qubit qi, half of (a,m) space
        int p = 9 - qi;
        float cr = 0.f, ci = 0.f, zz = 0.f;
        int start = half * 4096 + lane;
        #pragma unroll 4
        for (int pk_ = start; pk_ < start - lane + 4096; pk_ += 32) {
            int a = pk_ >> 9, m = pk_ & 511;
            int s0 = ((m >> p) << (p+1)) | (m & ((1 << p) - 1));
            int f0 = (a << 10) | s0;
            float2 a0 = st[f0];
            float2 a1 = st[f0 | (1 << p)];
            cr += a0.x*a1.x + a0.y*a1.y;
            ci += a0.x*a1.y - a0.y*a1.x;
            zz += (a0.x*a0.x + a0.y*a0.y) - (a1.x*a1.x + a1.y*a1.y);
        }
        #pragma unroll
        for (int off = 16; off; off >>= 1) {
            cr += __shfl_down_sync(0xffffffffu, cr, off);
            ci += __shfl_down_sync(0xffffffffu, ci, off);
            zz += __shfl_down_sync(0xffffffffu, zz, off);
        }
        if (lane == 0) { red[w][0] = cr; red[w][1] = ci; red[w][2] = zz; }
    }
    __syncthreads();
    if (tid < 10) {
        ex[tid]      = 2.f*(red[tid][0] + red[tid+10][0]);
        ex[10 + tid] = 2.f*(red[tid][1] + red[tid+10][1]);
        ex[20 + tid] =      red[tid][2] + red[tid+10][2];
    }
    __syncthreads();
    if (tid < ODIM) {
        float acc = b_out[tid];
        #pragma unroll
        for (int j = 0; j < 30; ++j) acc += W_out[tid*30 + j] * ex[j];
        out[b*ODIM + tid] = acc;
    }
}

// ------------------------------------------------------------ launch --------
extern "C" void kernel_launch(void* const* d_in, const int* in_sizes, int n_in,
                              void* d_out, int out_size)
{
    const float* x       = (const float*)d_in[0];
    const float* W_fp    = (const float*)d_in[1];
    const float* b_fp    = (const float*)d_in[2];
    const float* prep_p  = (const float*)d_in[3];
    const float* sig_ang = (const float*)d_in[4];
    const float* qff_p   = (const float*)d_in[5];
    const float* W_out   = (const float*)d_in[6];
    const float* b_out   = (const float*)d_in[7];
    float* out = (float*)d_out;

    k_pre<<<257, 256>>>(x, W_fp, b_fp, prep_p, sig_ang, qff_p);

    k_sel_f<<<256, 32>>>(2, 0, 1);   // k=0 forward (fused init)
    k_anc<<<256, 256>>>(0);
    k_sel_a<<<256, 32>>>(2);         // k=1 adjoint
    k_anc<<<256, 256>>>(1);
    k_sel_f<<<256, 32>>>(2, 0, 0);   // k=2 forward
    k_anc<<<256, 256>>>(2);

    k_sel_f<<<256, 32>>>(1, 1, 0);   // qff layer

    k_exp_out<<<Bsz, 640>>>(W_out, b_out, out);
}

// round 5
// speedup vs baseline: 1.9586x; 1.2834x over previous
#include <cuda_runtime.h>
#include <math.h>

#define Bsz 16
#define Tn 16
#define FDIM 64
#define ODIM 8
#define NQ 10
#define NA 4
#define NROTS 80
#define QROTS 40
#define NS 1024
#define NANC 16
#define STATE_PER_B (NS*NANC)
#define TOTAL_AMPS (Bsz*STATE_PER_B)

typedef unsigned long long u64;

__device__ float4 g_state4[TOTAL_AMPS/2];
#define G_STATE  ((float2*)g_state4)
#define G_STATEU ((u64*)g_state4)
__device__ float2 g_csn[Bsz*Tn*NROTS];
__device__ float2 g_qff[QROTS];
__device__ float2 g_M[3][256];
__device__ float2 g_v0[16];

// ------------------------------------------------------- packed f32x2 ops ---
__device__ __forceinline__ u64 pk2(float x, float y) {
    u64 r; asm("mov.b64 %0, {%1, %2};" : "=l"(r) : "f"(x), "f"(y)); return r;
}
__device__ __forceinline__ float2 upk(u64 a) {
    float2 f; asm("mov.b64 {%0, %1}, %2;" : "=f"(f.x), "=f"(f.y) : "l"(a)); return f;
}
__device__ __forceinline__ u64 mul2(u64 a, u64 b) {
    u64 d; asm("mul.rn.f32x2 %0, %1, %2;" : "=l"(d) : "l"(a), "l"(b)); return d;
}
__device__ __forceinline__ u64 fma2(u64 a, u64 b, u64 c) {
    u64 d; asm("fma.rn.f32x2 %0, %1, %2, %3;" : "=l"(d) : "l"(a), "l"(b), "l"(c)); return d;
}
__device__ __forceinline__ u64 swap2(u64 a) {
    float2 f = upk(a); return pk2(f.y, f.x);
}

// -------------------------------------------------- pre (angles + setup) ----
__global__ void __launch_bounds__(256) k_pre(const float* __restrict__ x,
                                             const float* __restrict__ Wfp,
                                             const float* __restrict__ bfp,
                                             const float* __restrict__ prep_p,
                                             const float* __restrict__ sig_ang,
                                             const float* __restrict__ qff_p)
{
    int tid = threadIdx.x;
    if (blockIdx.x < 256) {
        int bt = blockIdx.x;
        int b = bt >> 4, t = bt & 15;
        __shared__ float h[64];
        if (tid < 64) {
            int f = tid;
            int k = f >> 1;
            float div = expf((float)(2*k) * (-logf(10000.0f) / 64.0f));
            float arg = (float)t * div;
            float pe = (f & 1) ? cosf(arg) : sinf(arg);
            h[f] = x[(b*64 + f)*16 + t] + pe;
        }
        __syncthreads();
        if (tid < NROTS) {
            float acc = bfp[tid];
            const float* w = Wfp + tid*64;
            #pragma unroll
            for (int f = 0; f < 64; ++f) acc += h[f]*w[f];
            float sg = 1.0f / (1.0f + expf(-acc));
            float sn, cs;
            sincosf(3.14159265358979323846f * sg, &sn, &cs);
            g_csn[bt*NROTS + tid] = make_float2(cs, sn);
        }
        return;
    }
    __shared__ float2 sU[16][16];
    int t = tid;
    if (t < 16) {
        float2 v[16];
        #pragma unroll
        for (int i = 0; i < 16; ++i) v[i] = make_float2(0.f, 0.f);
        v[t] = make_float2(1.f, 0.f);
        for (int ly = 0; ly < 4; ++ly) {
            for (int qi = 0; qi < 4; ++qi) {
                int p = 3 - qi;
                float thy = prep_p[(ly*4 + qi)*2 + 0];
                float thz = prep_p[(ly*4 + qi)*2 + 1];
                float c, s;
                sincosf(0.5f*thy, &s, &c);
                for (int m = 0; m < 8; ++m) {
                    int i0 = ((m >> p) << (p+1)) | (m & ((1 << p) - 1));
                    int i1 = i0 | (1 << p);
                    float2 a0 = v[i0], a1 = v[i1];
                    v[i0] = make_float2(c*a0.x - s*a1.x, c*a0.y - s*a1.y);
                    v[i1] = make_float2(s*a0.x + c*a1.x, s*a0.y + c*a1.y);
                }
                float cz, sz;
                sincosf(0.5f*thz, &sz, &cz);
                for (int i = 0; i < 16; ++i) {
                    float im = ((i >> p) & 1) ? sz : -sz;
                    float2 a = v[i];
                    v[i] = make_float2(cz*a.x - im*a.y, cz*a.y + im*a.x);
                }
            }
            for (int i = 0; i < 3; ++i) {
                int pc = 3 - i, pt = 2 - i;
                for (int idx = 0; idx < 16; ++idx) {
                    if (((idx >> pc) & 1) == 1 && ((idx >> pt) & 1) == 0) {
                        int j = idx | (1 << pt);
                        float2 tmp = v[idx]; v[idx] = v[j]; v[j] = tmp;
                    }
                }
            }
        }
        #pragma unroll
        for (int r = 0; r < 16; ++r) sU[r][t] = v[r];
    }
    __syncthreads();
    if (t < 16) {
        float c0, s0;
        sincosf(sig_ang[0], &s0, &c0);
        float2 u = sU[t][0];
        g_v0[t] = make_float2(c0*u.x - s0*u.y, c0*u.y + s0*u.x);
    }
    if (t >= 192 && t < 192 + QROTS) {
        float c, s;
        sincosf(0.5f * qff_p[t - 192], &s, &c);
        g_qff[t - 192] = make_float2(c, s);
    }
    {
        int j = t >> 4, k = t & 15;
        for (int m = 0; m < 2; ++m) {
            float cp, sp;
            sincosf(sig_ang[m+1], &sp, &cp);
            float2 acc = make_float2(0.f, 0.f);
            #pragma unroll
            for (int a = 0; a < 16; ++a) {
                float2 uja = sU[j][a];
                float2 uka = sU[k][a];
                float dr = cp, di = (a == 0) ? sp : -sp;
                float2 dc = make_float2(dr*uka.x + di*uka.y, di*uka.x - dr*uka.y);
                acc.x += uja.x*dc.x - uja.y*dc.y;
                acc.y += uja.x*dc.y + uja.y*dc.x;
            }
            g_M[m][j*16 + k] = acc;
        }
        float cp, sp;
        sincosf(sig_ang[3], &sp, &cp);
        float dr = cp, di = (j == 0) ? sp : -sp;
        float2 u2 = sU[k][j];
        g_M[2][j*16 + k] = make_float2(dr*u2.x + di*u2.y, di*u2.x - dr*u2.y);
    }
}

// ------------------------------------------------------- gate primitives ----
// layout: amplitude s: lane = s[4:0], reg = s[7:5] (8 u64/lane), warp = s[9:8].

template<int PB>      // reg-bit RY, PB in 0..2
__device__ __forceinline__ void ry_reg(u64* v, float cc, float ss)
{
    u64 cc2 = pk2(cc, cc), ss2 = pk2(ss, ss), nss2 = pk2(-ss, -ss);
    #pragma unroll
    for (int m = 0; m < 4; ++m) {
        int i0 = ((m >> PB) << (PB+1)) | (m & ((1 << PB) - 1));
        int i1 = i0 | (1 << PB);
        u64 a0 = v[i0], a1 = v[i1];
        v[i0] = fma2(cc2, a0, mul2(nss2, a1));
        v[i1] = fma2(cc2, a1, mul2(ss2, a0));
    }
}

__device__ __forceinline__ void ry_lane(u64* v, int pl, float cc, float ss, int lane)
{
    float sg = ((lane >> pl) & 1) ? ss : -ss;
    u64 cc2 = pk2(cc, cc), sg2 = pk2(sg, sg);
    int mk = 1 << pl;
    #pragma unroll
    for (int q = 0; q < 8; ++q) {
        float2 f = upk(v[q]);
        float px = __shfl_xor_sync(0xffffffffu, f.x, mk);
        float py = __shfl_xor_sync(0xffffffffu, f.y, mk);
        v[q] = fma2(cc2, v[q], mul2(sg2, pk2(px, py)));
    }
}

template<int PCB, int PTB>    // reg-reg CRX
__device__ __forceinline__ void crx_rr(u64* v, float cc, float ss)
{
    u64 cc2 = pk2(cc, cc), ssv2 = pk2(ss, -ss);
    #pragma unroll
    for (int i = 0; i < 8; ++i) {
        if ((((i >> PCB) & 1) == 1) && (((i >> PTB) & 1) == 0)) {
            int i1 = i | (1 << PTB);
            u64 a0 = v[i], a1 = v[i1];
            v[i]  = fma2(cc2, a0, mul2(ssv2, swap2(a1)));
            v[i1] = fma2(cc2, a1, mul2(ssv2, swap2(a0)));
        }
    }
}

// shuffle-target CRX with arbitrary per-thread activity predicate
__device__ __forceinline__ void crx_shfl(u64* v, int pt, bool act, float cc, float ss)
{
    float ccl = act ? cc : 1.f, ssl = act ? ss : 0.f;
    u64 cc2 = pk2(ccl, ccl), ssv2 = pk2(ssl, -ssl);
    int mk = 1 << pt;
    #pragma unroll
    for (int q = 0; q < 8; ++q) {
        float2 f = upk(v[q]);
        float px = __shfl_xor_sync(0xffffffffu, f.x, mk);
        float py = __shfl_xor_sync(0xffffffffu, f.y, mk);
        v[q] = fma2(cc2, v[q], mul2(ssv2, pk2(py, px)));
    }
}

template<int PCB>     // control reg bit, target lane bit
__device__ __forceinline__ void crx_rl(u64* v, int pt, float cc, float ss)
{
    u64 cc2 = pk2(cc, cc), ssv2 = pk2(ss, -ss);
    int mk = 1 << pt;
    #pragma unroll
    for (int q = 0; q < 8; ++q) {
        if ((q >> PCB) & 1) {
            float2 f = upk(v[q]);
            float px = __shfl_xor_sync(0xffffffffu, f.x, mk);
            float py = __shfl_xor_sync(0xffffffffu, f.y, mk);
            v[q] = fma2(cc2, v[q], mul2(ssv2, pk2(py, px)));
        }
    }
}

template<int PTB>     // arbitrary activity predicate control, target reg bit
__device__ __forceinline__ void crx_reg_tgt(u64* v, bool act, float cc, float ss)
{
    float ccl = act ? cc : 1.f, ssl = act ? ss : 0.f;
    u64 cc2 = pk2(ccl, ccl), ssv2 = pk2(ssl, -ssl);
    #pragma unroll
    for (int m = 0; m < 4; ++m) {
        int i0 = ((m >> PTB) << (PTB+1)) | (m & ((1 << PTB) - 1));
        int i1 = i0 | (1 << PTB);
        u64 a0 = v[i0], a1 = v[i1];
        v[i0] = fma2(cc2, a0, mul2(ssv2, swap2(a1)));
        v[i1] = fma2(cc2, a1, mul2(ssv2, swap2(a0)));
    }
}

// ----- cross-warp exchange gates (double-buffered smem, 1 bar each) ---------
struct Xch {
    u64* base; int tog; int tid;
    __device__ __forceinline__ u64* next() { u64* p = base + ((tog & 1) << 10); ++tog; return p; }
};

// RY on warp bit wb
__device__ __forceinline__ void ry_warp(u64* v, Xch& X, int wb, float cc, float ss)
{
    u64* b = X.next();
    int tid = X.tid, xv = 32 << wb;
    #pragma unroll
    for (int i = 0; i < 8; ++i) b[i*128 + tid] = v[i];
    __syncthreads();
    float sg = ((tid >> (5 + wb)) & 1) ? ss : -ss;
    u64 cc2 = pk2(cc, cc), sg2 = pk2(sg, sg);
    #pragma unroll
    for (int i = 0; i < 8; ++i)
        v[i] = fma2(cc2, v[i], mul2(sg2, b[i*128 + (tid ^ xv)]));
}

// CRX with target on warp bit twb; act = control predicate (partner has same act)
__device__ __forceinline__ void crx_warp_tgt(u64* v, Xch& X, int twb, bool act, float cc, float ss)
{
    u64* b = X.next();
    int tid = X.tid, xv = 32 << twb;
    #pragma unroll
    for (int i = 0; i < 8; ++i) b[i*128 + tid] = v[i];
    __syncthreads();
    float ccl = act ? cc : 1.f, ssl = act ? ss : 0.f;
    u64 cc2 = pk2(ccl, ccl), ssv2 = pk2(ssl, -ssl);
    #pragma unroll
    for (int i = 0; i < 8; ++i)
        v[i] = fma2(cc2, v[i], mul2(ssv2, swap2(b[i*128 + (tid ^ xv)])));
}

// CRX control on reg bit 2 (regs 4..7), target warp bit twb
__device__ __forceinline__ void crx_rw(u64* v, Xch& X, int twb, float cc, float ss)
{
    u64* b = X.next();
    int tid = X.tid, xv = 32 << twb;
    #pragma unroll
    for (int i = 0; i < 4; ++i) b[i*128 + tid] = v[4 + i];
    __syncthreads();
    u64 cc2 = pk2(cc, cc), ssv2 = pk2(ss, -ss);
    #pragma unroll
    for (int i = 0; i < 4; ++i)
        v[4 + i] = fma2(cc2, v[4 + i], mul2(ssv2, swap2(b[i*128 + (tid ^ xv)])));
}

// -------------------------------------------------------- layer pieces ------
// ang[q] acts on bit 9-q.  bits: lane 0-4 (pl), reg 5-7 (PB 0-2), warp 8-9 (wb 0-1)
#define SS(A) (sgn*(A).y)

__device__ __forceinline__ void ry_all(u64* v, Xch& X, const float2* __restrict__ ang,
                                       float sgn, int lane)
{
    ry_warp(v, X, 1, ang[0].x, SS(ang[0]));      // q0 -> bit9
    ry_warp(v, X, 0, ang[1].x, SS(ang[1]));      // q1 -> bit8
    ry_reg<2>(v, ang[2].x, SS(ang[2]));          // q2 -> bit7
    ry_reg<1>(v, ang[3].x, SS(ang[3]));
    ry_reg<0>(v, ang[4].x, SS(ang[4]));
    #pragma unroll 1
    for (int pl = 4; pl >= 0; --pl) {            // q5..q9 -> lane bits 4..0
        float2 cs = ang[9 - pl];
        ry_lane(v, pl, cs.x, sgn*cs.y, lane);
    }
}

// ring A: gates k=0..9 = (ctrl bit k, tgt bit k-1 mod 10), angle ang[k]
__device__ __forceinline__ void ring_a(u64* v, Xch& X, const float2* __restrict__ ang,
                                       float sgn, int lane, int tid, bool rev)
{
    if (!rev) {
        crx_warp_tgt(v, X, 1, lane & 1, ang[0].x, SS(ang[0]));              // (0,9)
        #pragma unroll 1
        for (int j = 1; j <= 4; ++j)
            crx_shfl(v, j-1, (lane >> j) & 1, ang[j].x, SS(ang[j]));        // (j,j-1) lane
        crx_rl<0>(v, 4, ang[5].x, SS(ang[5]));                              // (5,4)
        crx_rr<1,0>(v, ang[6].x, SS(ang[6]));                               // (6,5)
        crx_rr<2,1>(v, ang[7].x, SS(ang[7]));                               // (7,6)
        crx_reg_tgt<2>(v, (tid >> 5) & 1, ang[8].x, SS(ang[8]));            // (8,7)
        crx_warp_tgt(v, X, 0, (tid >> 6) & 1, ang[9].x, SS(ang[9]));        // (9,8)
    } else {
        crx_warp_tgt(v, X, 0, (tid >> 6) & 1, ang[9].x, SS(ang[9]));
        crx_reg_tgt<2>(v, (tid >> 5) & 1, ang[8].x, SS(ang[8]));
        crx_rr<2,1>(v, ang[7].x, SS(ang[7]));
        crx_rr<1,0>(v, ang[6].x, SS(ang[6]));
        crx_rl<0>(v, 4, ang[5].x, SS(ang[5]));
        #pragma unroll 1
        for (int j = 4; j >= 1; --j)
            crx_shfl(v, j-1, (lane >> j) & 1, ang[j].x, SS(ang[j]));
        crx_warp_tgt(v, X, 1, lane & 1, ang[0].x, SS(ang[0]));
    }
}

// ring B: gates (0,1),(9,0),(8,9),(7,8),(6,7),(5,6),(4,5),(3,4),(2,3),(1,2), angle ang[k]
__device__ __forceinline__ void ring_b(u64* v, Xch& X, const float2* __restrict__ ang,
                                       float sgn, int lane, int tid, bool rev)
{
    if (!rev) {
        crx_shfl(v, 1, lane & 1, ang[0].x, SS(ang[0]));                     // (0,1)
        crx_shfl(v, 0, (tid >> 6) & 1, ang[1].x, SS(ang[1]));               // (9,0) warp ctrl
        crx_warp_tgt(v, X, 1, (tid >> 5) & 1, ang[2].x, SS(ang[2]));        // (8,9)
        crx_rw(v, X, 0, ang[3].x, SS(ang[3]));                              // (7,8)
        crx_rr<1,2>(v, ang[4].x, SS(ang[4]));                               // (6,7)
        crx_rr<0,1>(v, ang[5].x, SS(ang[5]));                               // (5,6)
        crx_reg_tgt<0>(v, (lane >> 4) & 1, ang[6].x, SS(ang[6]));           // (4,5)
        #pragma unroll 1
        for (int j = 7; j <= 9; ++j)                                        // (3,4),(2,3),(1,2)
            crx_shfl(v, 11-j, (lane >> (10-j)) & 1, ang[j].x, SS(ang[j]));
    } else {
        #pragma unroll 1
        for (int j = 9; j >= 7; --j)
            crx_shfl(v, 11-j, (lane >> (10-j)) & 1, ang[j].x, SS(ang[j]));
        crx_reg_tgt<0>(v, (lane >> 4) & 1, ang[6].x, SS(ang[6]));
        crx_rr<0,1>(v, ang[5].x, SS(ang[5]));
        crx_rr<1,2>(v, ang[4].x, SS(ang[4]));
        crx_rw(v, X, 0, ang[3].x, SS(ang[3]));
        crx_warp_tgt(v, X, 1, (tid >> 5) & 1, ang[2].x, SS(ang[2]));
        crx_shfl(v, 0, (tid >> 6) & 1, ang[1].x, SS(ang[1]));
        crx_shfl(v, 1, lane & 1, ang[0].x, SS(ang[0]));
    }
}

// ------------------------------------------------------------- select -------
__global__ void __launch_bounds__(128) k_sel_f(int nlayers, int useQff, int initFlag)
{
    int c = blockIdx.x;
    int tid = threadIdx.x;
    int lane = tid & 31;
    const float sgn = 1.f;
    __shared__ float2 sang[80];
    __shared__ u64 xbuf[2048];
    {
        const float2* src = useQff ? g_qff : (g_csn + c*NROTS);
        int ntot = nlayers * 40;
        if (tid < ntot) sang[tid] = src[tid];
    }
    __syncthreads();

    Xch X{xbuf, 0, tid};
    u64 v[8];
    u64* gb = G_STATEU + ((size_t)c << 10);
    int base = (tid >> 5) * 256 + lane;
    if (initFlag) {
        #pragma unroll
        for (int q = 0; q < 8; ++q) v[q] = 0ull;
        if (tid == 0) { float2 f = g_v0[c & 15]; v[0] = pk2(f.x, f.y); }
    } else {
        #pragma unroll
        for (int q = 0; q < 8; ++q) v[q] = gb[base + q*32];
    }

    #pragma unroll 1
    for (int l = 0; l < nlayers; ++l) {
        const float2* a = sang + 40*l;
        ry_all(v, X, a, sgn, lane);
        ring_a(v, X, a + 10, sgn, lane, tid, false);
        ry_all(v, X, a + 20, sgn, lane);
        ring_b(v, X, a + 30, sgn, lane, tid, false);
    }

    #pragma unroll
    for (int q = 0; q < 8; ++q) gb[base + q*32] = v[q];
}

__global__ void __launch_bounds__(128) k_sel_a(int nlayers)
{
    int c = blockIdx.x;
    int tid = threadIdx.x;
    int lane = tid & 31;
    const float sgn = -1.f;
    __shared__ float2 sang[80];
    __shared__ u64 xbuf[2048];
    {
        const float2* src = g_csn + c*NROTS;
        int ntot = nlayers * 40;
        if (tid < ntot) sang[tid] = src[tid];
    }
    __syncthreads();

    Xch X{xbuf, 0, tid};
    u64 v[8];
    u64* gb = G_STATEU + ((size_t)c << 10);
    int base = (tid >> 5) * 256 + lane;
    #pragma unroll
    for (int q = 0; q < 8; ++q) v[q] = gb[base + q*32];

    #pragma unroll 1
    for (int l = nlayers - 1; l >= 0; --l) {
        const float2* a = sang + 40*l;
        ring_b(v, X, a + 30, sgn, lane, tid, true);
        ry_all(v, X, a + 20, sgn, lane);
        ring_a(v, X, a + 10, sgn, lane, tid, true);
        ry_all(v, X, a, sgn, lane);
    }

    #pragma unroll
    for (int q = 0; q < 8; ++q) gb[base + q*32] = v[q];
}

// ---------------------------------------------------------- ancilla mat -----
__global__ void __launch_bounds__(256) k_anc(int mi)
{
    int bk = blockIdx.x;               // 16 b * 16 s-groups of 64
    int b = bk >> 4, s0 = (bk & 15) << 6;
    __shared__ float2 vin[16][64];
    __shared__ float2 sM[256];
    int tid = threadIdx.x;
    int a = tid >> 4, sj = tid & 15;
    sM[tid] = g_M[mi][tid];
    size_t base = (((size_t)(b*16 + a)) << 10) + s0 + sj;
    vin[a][sj]      = G_STATE[base];
    vin[a][sj + 16] = G_STATE[base + 16];
    vin[a][sj + 32] = G_STATE[base + 32];
    vin[a][sj + 48] = G_STATE[base + 48];
    __syncthreads();
    float2 acc0 = make_float2(0.f,0.f), acc1 = make_float2(0.f,0.f);
    float2 acc2 = make_float2(0.f,0.f), acc3 = make_float2(0.f,0.f);
    #pragma unroll
    for (int k2 = 0; k2 < 16; ++k2) {
        float2 m = sM[a*16 + k2];
        float2 w0 = vin[k2][sj],      w1 = vin[k2][sj + 16];
        float2 w2 = vin[k2][sj + 32], w3 = vin[k2][sj + 48];
        acc0.x += m.x*w0.x - m.y*w0.y; acc0.y += m.x*w0.y + m.y*w0.x;
        acc1.x += m.x*w1.x - m.y*w1.y; acc1.y += m.x*w1.y + m.y*w1.x;
        acc2.x += m.x*w2.x - m.y*w2.y; acc2.y += m.x*w2.y + m.y*w2.x;
        acc3.x += m.x*w3.x - m.y*w3.y; acc3.y += m.x*w3.y + m.y*w3.x;
    }
    G_STATE[base]      = acc0;
    G_STATE[base + 16] = acc1;
    G_STATE[base + 32] = acc2;
    G_STATE[base + 48] = acc3;
}

// ------------------------------------------------- expvals + output GEMM ----
__global__ void __launch_bounds__(640) k_exp_out(const float* __restrict__ W_out,
                                                 const float* __restrict__ b_out,
                                                 float* __restrict__ out)
{
    int b = blockIdx.x;
    int tid = threadIdx.x, w = tid >> 5, lane = tid & 31;
    const float2* st = G_STATE + ((size_t)b << 14);
    __shared__ float red[20][3];
    __shared__ float ex[30];

    {
        int qi = w % 10, half = w / 10;
        int p = 9 - qi;
        float cr = 0.f, ci = 0.f, zz = 0.f;
        int start = half * 4096 + lane;
        #pragma unroll 4
        for (int pk_ = start; pk_ < start - lane + 4096; pk_ += 32) {
            int a = pk_ >> 9, m = pk_ & 511;
            int s0 = ((m >> p) << (p+1)) | (m & ((1 << p) - 1));
            int f0 = (a << 10) | s0;
            float2 a0 = st[f0];
            float2 a1 = st[f0 | (1 << p)];
            cr += a0.x*a1.x + a0.y*a1.y;
            ci += a0.x*a1.y - a0.y*a1.x;
            zz += (a0.x*a0.x + a0.y*a0.y) - (a1.x*a1.x + a1.y*a1.y);
        }
        #pragma unroll
        for (int off = 16; off; off >>= 1) {
            cr += __shfl_down_sync(0xffffffffu, cr, off);
            ci += __shfl_down_sync(0xffffffffu, ci, off);
            zz += __shfl_down_sync(0xffffffffu, zz, off);
        }
        if (lane == 0) { red[w][0] = cr; red[w][1] = ci; red[w][2] = zz; }
    }
    __syncthreads();
    if (tid < 10) {
        ex[tid]      = 2.f*(red[tid][0] + red[tid+10][0]);
        ex[10 + tid] = 2.f*(red[tid][1] + red[tid+10][1]);
        ex[20 + tid] =      red[tid][2] + red[tid+10][2];
    }
    __syncthreads();
    if (tid < ODIM) {
        float acc = b_out[tid];
        #pragma unroll
        for (int j = 0; j < 30; ++j) acc += W_out[tid*30 + j] * ex[j];
        out[b*ODIM + tid] = acc;
    }
}

// ------------------------------------------------------------ launch --------
extern "C" void kernel_launch(void* const* d_in, const int* in_sizes, int n_in,
                              void* d_out, int out_size)
{
    const float* x       = (const float*)d_in[0];
    const float* W_fp    = (const float*)d_in[1];
    const float* b_fp    = (const float*)d_in[2];
    const float* prep_p  = (const float*)d_in[3];
    const float* sig_ang = (const float*)d_in[4];
    const float* qff_p   = (const float*)d_in[5];
    const float* W_out   = (const float*)d_in[6];
    const float* b_out   = (const float*)d_in[7];
    float* out = (float*)d_out;

    k_pre<<<257, 256>>>(x, W_fp, b_fp, prep_p, sig_ang, qff_p);

    k_sel_f<<<256, 128>>>(2, 0, 1);   // k=0 forward (fused init)
    k_anc<<<256, 256>>>(0);
    k_sel_a<<<256, 128>>>(2);         // k=1 adjoint
    k_anc<<<256, 256>>>(1);
    k_sel_f<<<256, 128>>>(2, 0, 0);   // k=2 forward
    k_anc<<<256, 256>>>(2);

    k_sel_f<<<256, 128>>>(1, 1, 0);   // qff layer

    k_exp_out<<<Bsz, 640>>>(W_out, b_out, out);
}